// round 12
// baseline (speedup 1.0000x reference)
#include <cuda_runtime.h>

#define TPB     256
#define NBINS   64
#define SBINS   56            // max bin = ceil(31.5*sqrt(3)) = 55
#define HSTRIDE 258           // u16 per-bin stride = 129 words (odd) -> bank
                              //  = (tid/2 + bin) % 32: no fixed lane conflicts
#define HWORDS  (SBINS * HSTRIDE / 2)   // 7224 words = 28,896 B
#define CPS     6             // CTAs per SM
#define GRID    (148 * CPS)   // 888 blocks, single wave
#define NUNITS  1024          // units: row quads (4k .. 4k+3)

// Scratch (allocation-free __device__ globals). Zero at entry of every
// launch; the finalizing block resets them (graph-replay safe).
__device__ int      g_hist[NBINS];
__device__ unsigned g_done = 0;
__device__ unsigned g_unit = 0;

// Coordinates pre-scaled by 31.5: bin = ceil(sqrt(dx^2+dy^2+dz^2)).
// Max scaled distance = 31.5*sqrt(3) = 54.56 < 55.5 -> no clamp needed.
__device__ __forceinline__ int pair_bin(float dx, float dy, float dz) {
    const float s = dx * dx + dy * dy + dz * dz;   // FMA ok (tol 1e-3)
    float r;
    asm("sqrt.approx.f32 %0, %1;" : "=f"(r) : "f"(s));  // s==0 -> 0 -> bin 0
    return __float2int_ru(r);
}

__global__ __launch_bounds__(TPB, CPS)
void ecc_kernel(const float* __restrict__ x, float* __restrict__ out, int n) {
    __shared__ unsigned short sh[SBINS * HSTRIDE];
    __shared__ int      s_u;
    __shared__ float    s_wsum;
    __shared__ unsigned s_last;

    const int tid = threadIdx.x;
    unsigned* h32 = (unsigned*)sh;
    for (int k = tid; k < HWORDS; k += TPB) h32[k] = 0u;

    unsigned short* myh = sh + tid;   // column tid; +258 halfwords per bin

    // Dynamic queue over row-quads; low k = longest unit, fetched first (LPT)
    for (;;) {
        if (tid == 0) s_u = (int)atomicAdd(&g_unit, 1u);
        __syncthreads();                     // also covers zero-init (1st iter)
        const int k = s_u;
        if (k >= NUNITS) break;

        const int i0 = 4 * k;
        const float p0x = 31.5f * __ldg(&x[3 * i0 + 0]);
        const float p0y = 31.5f * __ldg(&x[3 * i0 + 1]);
        const float p0z = 31.5f * __ldg(&x[3 * i0 + 2]);
        const float p1x = 31.5f * __ldg(&x[3 * i0 + 3]);
        const float p1y = 31.5f * __ldg(&x[3 * i0 + 4]);
        const float p1z = 31.5f * __ldg(&x[3 * i0 + 5]);
        const float p2x = 31.5f * __ldg(&x[3 * i0 + 6]);
        const float p2y = 31.5f * __ldg(&x[3 * i0 + 7]);
        const float p2z = 31.5f * __ldg(&x[3 * i0 + 8]);
        const float p3x = 31.5f * __ldg(&x[3 * i0 + 9]);
        const float p3y = 31.5f * __ldg(&x[3 * i0 + 10]);
        const float p3z = 31.5f * __ldg(&x[3 * i0 + 11]);

        // 6 intra-quad corner pairs from registers (no reloads)
        if (tid < 6) {
            float ax, ay, az, cx, cy, cz;
            if (tid < 3)      { ax = p0x; ay = p0y; az = p0z; }
            else if (tid < 5) { ax = p1x; ay = p1y; az = p1z; }
            else              { ax = p2x; ay = p2y; az = p2z; }
            if (tid == 0)      { cx = p1x; cy = p1y; cz = p1z; }
            else if (tid == 1 || tid == 3) { cx = p2x; cy = p2y; cz = p2z; }
            else               { cx = p3x; cy = p3y; cz = p3z; }
            const int b = pair_bin(ax - cx, ay - cy, az - cz);
            myh[b * HSTRIDE] += 1;
        }

        // Shared j-range: one load -> FOUR pairs
        #pragma unroll 4
        for (int j = i0 + 4 + tid; j < n; j += TPB) {
            const float qx = 31.5f * __ldg(&x[3 * j + 0]);
            const float qy = 31.5f * __ldg(&x[3 * j + 1]);
            const float qz = 31.5f * __ldg(&x[3 * j + 2]);
            const int b0 = pair_bin(p0x - qx, p0y - qy, p0z - qz);
            const int b1 = pair_bin(p1x - qx, p1y - qy, p1z - qz);
            const int b2 = pair_bin(p2x - qx, p2y - qy, p2z - qz);
            const int b3 = pair_bin(p3x - qx, p3y - qy, p3z - qz);
            myh[b0 * HSTRIDE] += 1;
            myh[b1 * HSTRIDE] += 1;
            myh[b2 * HSTRIDE] += 1;
            myh[b3 * HSTRIDE] += 1;
        }
        __syncthreads();                     // protect s_u for next fetch
    }
    __syncthreads();                         // RMWs visible to reducers

    // Block-reduce [56][129 words] -> g_hist: 4 threads/bin, rotated banks
    if (tid < SBINS * 4) {
        const int b = tid >> 2;
        const int q = tid & 3;
        const unsigned* hb = h32 + b * (HSTRIDE / 2);   // 129 words
        unsigned sum = 0;
        #pragma unroll
        for (int kk = 0; kk < 33; kk++) {
            const int w = q * 33 + kk;                  // 0..131
            if (w < HSTRIDE / 2) {
                const unsigned v = hb[w];
                sum += (v & 0xFFFFu) + (v >> 16);
            }
        }
        sum += __shfl_xor_sync(0xffffffffu, sum, 1);
        sum += __shfl_xor_sync(0xffffffffu, sum, 2);
        if (q == 0 && sum) atomicAdd(&g_hist[b], (int)sum);
    }
    __syncthreads();

    // Last-done block: parallel 64-bin read + 2-warp shfl scan
    if (tid == 0) {
        __threadfence();
        s_last = (atomicAdd(&g_done, 1u) == (unsigned)GRID - 1u);
    }
    __syncthreads();
    if (s_last) {
        float v = 0.0f;
        if (tid < NBINS) {
            const int h = atomicAdd(&g_hist[tid], 0);   // 64 parallel reads
            v = -(float)h;
            if (tid == 0) v += (float)n;                // +n vertices at filt 0
            #pragma unroll
            for (int d = 1; d < 32; d <<= 1) {          // inclusive warp scan
                const float t = __shfl_up_sync(0xffffffffu, v, d);
                if ((tid & 31) >= d) v += t;
            }
            if (tid == 31) s_wsum = v;                  // warp0 total
        }
        __syncthreads();
        if (tid < NBINS) {
            if (tid >= 32) v += s_wsum;
            out[tid] = v;
            g_hist[tid] = 0;                            // reset for next replay
        }
        if (tid == 0) { g_unit = 0; g_done = 0; }
    }
}

extern "C" void kernel_launch(void* const* d_in, const int* in_sizes, int n_in,
                              void* d_out, int out_size) {
    const float* x = (const float*)d_in[0];
    float* out = (float*)d_out;
    const int n = in_sizes[0] / 3;   // 4096
    ecc_kernel<<<GRID, TPB>>>(x, out, n);
}

// round 14
// speedup vs baseline: 1.1344x; 1.1344x over previous
#include <cuda_runtime.h>

#define TPB     256
#define NBINS   64
#define SBINS   56           // max bin = ceil(31.5*sqrt(3)) = 55
#define CPS     6            // CTAs per SM (42-reg cap, 48 warps/SM)
#define GRID    (148 * CPS)  // 888 blocks, single wave
#define NUNITS  1024         // units: row quads (4k .. 4k+3)

// Scratch (allocation-free __device__ globals). Zero at entry of every
// launch; the finalizing block resets them (graph-replay safe).
__device__ int      g_hist[NBINS];
__device__ unsigned g_done = 0;
__device__ unsigned g_unit = 0;

// Coordinates pre-scaled by 31.5: bin = ceil(sqrt(dx^2+dy^2+dz^2)).
// Max scaled distance = 31.5*sqrt(3) = 54.56 < 55.5 -> no clamp needed.
__device__ __forceinline__ int pair_bin(float dx, float dy, float dz) {
    const float s = dx * dx + dy * dy + dz * dz;   // FMA ok (tol 1e-3)
    float r;
    asm("sqrt.approx.f32 %0, %1;" : "=f"(r) : "f"(s));  // s==0 -> 0 -> bin 0
    return __float2int_ru(r);
}

__global__ __launch_bounds__(TPB, CPS)
void ecc_kernel(const float* __restrict__ x, float* __restrict__ out, int n) {
    // u16 hist, warp-pair interleaved: halfword idx =
    //   (w&1) + 2*lane + 64*(w>>1) + 256*bin
    // -> word = lane + 32*(w>>1) + 128*bin, bank = lane: CONFLICT-FREE for
    // every lane of every warp, any bin pattern. Warps 2m/2m+1 share words
    // but write disjoint u16 halves (no race).
    __shared__ unsigned short sh[SBINS * TPB];
    __shared__ int      s_u;
    __shared__ float    s_wsum;
    __shared__ unsigned s_last;

    const int tid  = threadIdx.x;
    const int lane = tid & 31;
    const int w    = tid >> 5;

    unsigned* h32 = (unsigned*)sh;
    #pragma unroll
    for (int k = tid; k < SBINS * TPB / 2; k += TPB) h32[k] = 0u;

    unsigned short* myh = sh + ((w & 1) + 2 * lane + 64 * (w >> 1));

    // Dynamic queue over row-quads; low k = longest unit, fetched first (LPT)
    for (;;) {
        if (tid == 0) s_u = (int)atomicAdd(&g_unit, 1u);
        __syncthreads();                     // also covers zero-init (1st iter)
        const int k = s_u;
        if (k >= NUNITS) break;

        const int i0 = 4 * k;
        const float p0x = 31.5f * __ldg(&x[3 * i0 + 0]);
        const float p0y = 31.5f * __ldg(&x[3 * i0 + 1]);
        const float p0z = 31.5f * __ldg(&x[3 * i0 + 2]);
        const float p1x = 31.5f * __ldg(&x[3 * i0 + 3]);
        const float p1y = 31.5f * __ldg(&x[3 * i0 + 4]);
        const float p1z = 31.5f * __ldg(&x[3 * i0 + 5]);
        const float p2x = 31.5f * __ldg(&x[3 * i0 + 6]);
        const float p2y = 31.5f * __ldg(&x[3 * i0 + 7]);
        const float p2z = 31.5f * __ldg(&x[3 * i0 + 8]);
        const float p3x = 31.5f * __ldg(&x[3 * i0 + 9]);
        const float p3y = 31.5f * __ldg(&x[3 * i0 + 10]);
        const float p3z = 31.5f * __ldg(&x[3 * i0 + 11]);

        // 6 intra-quad corner pairs from registers (no reloads)
        if (tid < 6) {
            float ax, ay, az, cx, cy, cz;
            if (tid < 3)      { ax = p0x; ay = p0y; az = p0z; }
            else if (tid < 5) { ax = p1x; ay = p1y; az = p1z; }
            else              { ax = p2x; ay = p2y; az = p2z; }
            if (tid == 0)      { cx = p1x; cy = p1y; cz = p1z; }
            else if (tid == 1 || tid == 3) { cx = p2x; cy = p2y; cz = p2z; }
            else               { cx = p3x; cy = p3y; cz = p3z; }
            const int b = pair_bin(ax - cx, ay - cy, az - cz);
            myh[b * TPB] += 1;
        }

        // Shared j-range: one load -> FOUR pairs
        #pragma unroll 2
        for (int j = i0 + 4 + tid; j < n; j += TPB) {
            const float qx = 31.5f * __ldg(&x[3 * j + 0]);
            const float qy = 31.5f * __ldg(&x[3 * j + 1]);
            const float qz = 31.5f * __ldg(&x[3 * j + 2]);
            const int b0 = pair_bin(p0x - qx, p0y - qy, p0z - qz);
            const int b1 = pair_bin(p1x - qx, p1y - qy, p1z - qz);
            const int b2 = pair_bin(p2x - qx, p2y - qy, p2z - qz);
            const int b3 = pair_bin(p3x - qx, p3y - qy, p3z - qz);
            myh[b0 * TPB] += 1;
            myh[b1 * TPB] += 1;
            myh[b2 * TPB] += 1;
            myh[b3 * TPB] += 1;
        }
        __syncthreads();                     // protect s_u for next fetch
    }
    __syncthreads();                         // RMWs visible to reducers

    // Block-reduce [56][128 words] -> g_hist: 4 threads/bin, rotated banks
    if (tid < SBINS * 4) {
        const int b = tid >> 2;
        const int q = tid & 3;
        const unsigned* hb = h32 + b * 128;
        unsigned sum = 0;
        #pragma unroll
        for (int kk = 0; kk < 32; kk++) {
            const unsigned v = hb[q * 32 + ((kk + tid) & 31)];
            sum += (v & 0xFFFFu) + (v >> 16);
        }
        sum += __shfl_xor_sync(0xffffffffu, sum, 1);
        sum += __shfl_xor_sync(0xffffffffu, sum, 2);
        if (q == 0 && sum) atomicAdd(&g_hist[b], (int)sum);
    }
    __syncthreads();

    // Last-done block: parallel 64-bin read + 2-warp shfl scan
    if (tid == 0) {
        __threadfence();
        s_last = (atomicAdd(&g_done, 1u) == (unsigned)GRID - 1u);
    }
    __syncthreads();
    if (s_last) {
        float v = 0.0f;
        if (tid < NBINS) {
            const int h = atomicAdd(&g_hist[tid], 0);   // 64 parallel reads
            v = -(float)h;
            if (tid == 0) v += (float)n;                // +n vertices at filt 0
            #pragma unroll
            for (int d = 1; d < 32; d <<= 1) {          // inclusive warp scan
                const float t = __shfl_up_sync(0xffffffffu, v, d);
                if ((tid & 31) >= d) v += t;
            }
            if (tid == 31) s_wsum = v;                  // warp0 total
        }
        __syncthreads();
        if (tid < NBINS) {
            if (tid >= 32) v += s_wsum;
            out[tid] = v;
            g_hist[tid] = 0;                            // reset for next replay
        }
        if (tid == 0) { g_unit = 0; g_done = 0; }
    }
}

extern "C" void kernel_launch(void* const* d_in, const int* in_sizes, int n_in,
                              void* d_out, int out_size) {
    const float* x = (const float*)d_in[0];
    float* out = (float*)d_out;
    const int n = in_sizes[0] / 3;   // 4096
    ecc_kernel<<<GRID, TPB>>>(x, out, n);
}